// round 2
// baseline (speedup 1.0000x reference)
#include <cuda_runtime.h>

#define HW_DIM 10
#define NUM_DEV 50
#define NUM_INT 101
#define ODIM 30

__global__ __launch_bounds__(32, 1)
void mhn_kernel(const float* __restrict__ x,
                const float* __restrict__ hw,
                const float* __restrict__ hw_emb,
                const float* __restrict__ expert_emb,
                float* __restrict__ out)
{
    const int lane = threadIdx.x;
    const unsigned full = 0xffffffffu;

    // ---- Issue ALL independent loads up front ----
    // Chain A root: x (one DRAM miss), then 50 independent gather loads.
    const float xv = __ldg(x);

    // Chain B roots: hw + two hw_emb rows per lane (independent of chain A).
    float h[HW_DIM], he0[HW_DIM], he1[HW_DIM];
#pragma unroll
    for (int j = 0; j < HW_DIM; ++j) h[j] = __ldg(hw + j);

    const float* p0 = hw_emb + lane * HW_DIM;
#pragma unroll
    for (int j = 0; j < HW_DIM; ++j) he0[j] = __ldg(p0 + j);

    const int e1i = lane + 32;
    const bool has1 = (e1i < NUM_DEV);
    const float* p1 = hw_emb + (has1 ? e1i : 0) * HW_DIM;
#pragma unroll
    for (int j = 0; j < HW_DIM; ++j) he1[j] = __ldg(p1 + j);

    // Chain A continuation: idx (depends only on xv) -> 50 gather loads,
    // prefetched into registers BEFORE any gate math so both DRAM chains overlap.
    const int idx = (int)rintf(xv * (float)(NUM_INT - 1));
    const int d = (lane < ODIM) ? lane : 0;  // lanes 30,31 load dim 0 harmlessly
    const float* gbase = expert_emb + (size_t)idx * ODIM + d;

    float v[NUM_DEV];
#pragma unroll
    for (int e = 0; e < NUM_DEV; ++e)
        v[e] = __ldg(gbase + (size_t)e * (NUM_INT * ODIM));

    // ---- Chain B compute: dots -> sin -> exp (no max-sub needed: sin in [-1,1]) ----
    const float inv_sqrt = 0.31622776601683794f; // 1/sqrt(10)

    float d0 = 0.f, d1 = 0.f;
#pragma unroll
    for (int j = 0; j < HW_DIM; ++j) {
        d0 = fmaf(h[j], he0[j], d0);
        d1 = fmaf(h[j], he1[j], d1);
    }
    const float g0 = __expf(__sinf(d0 * inv_sqrt));
    const float g1 = has1 ? __expf(__sinf(d1 * inv_sqrt)) : 0.f;

    // Sum reduction (runs concurrently with the FMA combine below in HW terms;
    // normalization deferred to the very end).
    float sum = g0 + g1;
#pragma unroll
    for (int o = 16; o > 0; o >>= 1)
        sum += __shfl_xor_sync(full, sum, o);

    // ---- Combine: gate broadcast via shuffle (no barrier), 2 accumulators ----
    float accA = 0.f, accB = 0.f;
#pragma unroll
    for (int e = 0; e < 32; e += 2) {
        accA = fmaf(__shfl_sync(full, g0, e),     v[e],     accA);
        accB = fmaf(__shfl_sync(full, g0, e + 1), v[e + 1], accB);
    }
#pragma unroll
    for (int e = 32; e < NUM_DEV; e += 2) {
        accA = fmaf(__shfl_sync(full, g1, e - 32), v[e],     accA);
        accB = fmaf(__shfl_sync(full, g1, e - 31), v[e + 1], accB);
    }

    if (lane < ODIM)
        out[lane] = __fdividef(accA + accB, sum);
}

extern "C" void kernel_launch(void* const* d_in, const int* in_sizes, int n_in,
                              void* d_out, int out_size)
{
    const float* x          = (const float*)d_in[0];
    const float* hw         = (const float*)d_in[1];
    const float* hw_emb     = (const float*)d_in[2];
    const float* expert_emb = (const float*)d_in[3];
    float* out = (float*)d_out;

    mhn_kernel<<<1, 32>>>(x, hw, hw_emb, expert_emb, out);
}